// round 15
// baseline (speedup 1.0000x reference)
#include <cuda_runtime.h>
#include <math.h>
#include <stdint.h>

#define BB 4
#define LL 2048
#define DD 1024
#define HH 16
#define HD 64

// Q prescale: 1/sqrt(64) * log2(e) -> softmax in exp2 domain.
#define QSCALE 0.1803368801111204f

// Scratch (device globals). All fp16 payloads stored as packed uint32 words.
__device__ float    g_qkv[(size_t)BB * LL * 3 * DD];       // fp16 words [M][1536]
__device__ float    g_att[(size_t)BB * LL * DD];           // fp16 words [M][512] (linear)
__device__ uint32_t g_xt  [(size_t)BB * LL * DD];          // x fp16 words (linear)
__device__ uint32_t g_wq  [(size_t)3 * DD * DD];           // Wqkv fp16 words (linear)
__device__ uint32_t g_wo  [(size_t)DD * DD];               // Wout fp16 words (linear)
__device__ uint32_t g_vt  [(size_t)BB * HH * HD * (LL/2)]; // V^T fp16 words [(b,h,hd)][1024]

// pos8 word permutation within an 8-word group — attention-internal layouts only.
__device__ __host__ __forceinline__ int pos8(int i) {
    return (i < 4) ? (i << 1) : ((i << 1) - 7);
}

__device__ __forceinline__ uint32_t pack_f16x2(float lo, float hi) {
    uint32_t r;
    asm("cvt.rn.f16x2.f32 %0, %1, %2;" : "=r"(r) : "f"(hi), "f"(lo));
    return r;
}

__device__ __forceinline__ void cp_async16(uint32_t smem_addr, const void* gptr) {
    asm volatile("cp.async.cg.shared.global [%0], [%1], 16;\n"
                 :: "r"(smem_addr), "l"(gptr));
}
__device__ __forceinline__ void cp_commit() {
    asm volatile("cp.async.commit_group;\n" ::: "memory");
}
template <int N>
__device__ __forceinline__ void cp_wait() {
    asm volatile("cp.async.wait_group %0;\n" :: "n"(N) : "memory");
}

// m16n8k16 f16 mma, f32 acc.
__device__ __forceinline__ void mma_f16(float* d, const uint32_t* a,
                                        uint32_t b0, uint32_t b1) {
    asm volatile(
        "mma.sync.aligned.m16n8k16.row.col.f32.f16.f16.f32 "
        "{%0,%1,%2,%3}, {%4,%5,%6,%7}, {%8,%9}, {%0,%1,%2,%3};\n"
        : "+f"(d[0]), "+f"(d[1]), "+f"(d[2]), "+f"(d[3])
        : "r"(a[0]), "r"(a[1]), "r"(a[2]), "r"(a[3]), "r"(b0), "r"(b1));
}

// ldmatrix x4 (non-transposed), b16.
__device__ __forceinline__ void ldsm_x4(uint32_t addr, uint32_t* r) {
    asm volatile("ldmatrix.sync.aligned.m8n8.x4.shared.b16 {%0,%1,%2,%3}, [%4];"
                 : "=r"(r[0]), "=r"(r[1]), "=r"(r[2]), "=r"(r[3]) : "r"(addr));
}

// ---------------------------------------------------------------------------
// Prepass: fp32 -> fp16 words (linear layout).
// ---------------------------------------------------------------------------
__global__ void conv_f16_kernel(const float* __restrict__ in,
                                uint32_t* __restrict__ out, int n8) {
    int i = blockIdx.x * blockDim.x + threadIdx.x;
    if (i >= n8) return;
    const float4 v0 = *(const float4*)(in + (size_t)i * 8);
    const float4 v1 = *(const float4*)(in + (size_t)i * 8 + 4);
    uint4 r;
    r.x = pack_f16x2(v0.x, v0.y);
    r.y = pack_f16x2(v0.z, v0.w);
    r.z = pack_f16x2(v1.x, v1.y);
    r.w = pack_f16x2(v1.z, v1.w);
    *(uint4*)(out + (size_t)i * 4) = r;
}

// ---------------------------------------------------------------------------
// fp16 GEMM (mma.sync m16n8k16 + ldmatrix), C = A @ W^T + bias.
// Block 128x128, 256 threads / 8 warps (2 row-bands x 4 col-bands),
// warp tile 64x32 (acc = 64 regs, same per-warp loop as R14). kTile 32 words,
// 2-stage cp.async, stride-36 rows (LDSM + cp.async phases conflict-free:
// chunk = (r + c) mod 8). 2 CTAs/SM = 16 warps = 4/SMSP; square tile restores
// minimal L2 traffic (A and W each read once per 128x128 output tile).
// MODE 0: fp32 out + bias. MODE 1: fp16 out, Q cols scaled, Q/K pos8, V linear.
// ---------------------------------------------------------------------------
#define GST 36
#define ABW (128 * GST)                  // A words per stage
#define STGW (2 * ABW)                   // stage words (A then W, each 128 rows)
#define SMEM_GEMM (2 * STGW * 4)         // 73728 B

template <int MODE>
__global__ __launch_bounds__(256, 2) void gemm_f16(
    const uint32_t* __restrict__ A, const uint32_t* __restrict__ W,
    const float* __restrict__ bias, float* __restrict__ C,
    int M, int N, int Kw)
{
    extern __shared__ uint32_t gsm[];

    const int tid = threadIdx.x;
    const int lane = tid & 31;
    const int ww = tid >> 5;
    const int wr = ww >> 2;          // 0..1 (64-row band)
    const int wc = ww & 3;           // 0..3 (32-col band)
    const int qr = lane >> 2;
    const int qc = lane & 3;
    const int bm = blockIdx.y * 128;
    const int bn = blockIdx.x * 128;

    float acc[4][4][4];
#pragma unroll
    for (int i = 0; i < 4; i++)
#pragma unroll
        for (int j = 0; j < 4; j++)
#pragma unroll
            for (int c = 0; c < 4; c++) acc[i][j][c] = 0.0f;

    const uint32_t sm_base = (uint32_t)__cvta_generic_to_shared(gsm);
    const int nkt = Kw / 32;

    // ldmatrix per-lane byte offsets within a stage:
    const uint32_t a_lane = (uint32_t)(((wr * 64 + (lane & 15)) * GST
                                        + (lane >> 4) * 4) * 4);
    const uint32_t b_lane = (uint32_t)(((wc * 32 + ((lane >> 4) << 3) + (lane & 7)) * GST
                                        + ((lane >> 3) & 1) * 4) * 4);

    auto stage = [&](int kt_idx, int s) {
#pragma unroll
        for (int i = 0; i < 4; i++) {       // A: 1024 chunks of 16B
            const int q = i * 256 + tid;
            const int r = q >> 3, c = q & 7;
            cp_async16(sm_base + (uint32_t)((s * STGW + r * GST + c * 4) * 4),
                       A + (size_t)(bm + r) * Kw + kt_idx * 32 + c * 4);
        }
#pragma unroll
        for (int i = 0; i < 4; i++) {       // W: 1024 chunks
            const int q = i * 256 + tid;
            const int r = q >> 3, c = q & 7;
            cp_async16(sm_base + (uint32_t)((s * STGW + ABW + r * GST + c * 4) * 4),
                       W + (size_t)(bn + r) * Kw + kt_idx * 32 + c * 4);
        }
        cp_commit();
    };

    stage(0, 0);

    for (int kt = 0; kt < nkt; kt++) {
        const int s = kt & 1;
        __syncthreads();   // all warps done reading buffer s^1 (iter kt-1)
        if (kt + 1 < nkt) { stage(kt + 1, s ^ 1); cp_wait<1>(); }
        else              { cp_wait<0>(); }
        __syncthreads();

        const uint32_t abase = sm_base + (uint32_t)(s * STGW * 4) + a_lane;
        const uint32_t bbase = sm_base + (uint32_t)((s * STGW + ABW) * 4) + b_lane;

#pragma unroll
        for (int st = 0; st < 4; st++) {
            uint32_t aa[4][4], bb[2][4];
#pragma unroll
            for (int mi = 0; mi < 4; mi++)
                ldsm_x4(abase + (uint32_t)(mi * 16 * GST * 4 + st * 32), aa[mi]);
#pragma unroll
            for (int p = 0; p < 2; p++)
                ldsm_x4(bbase + (uint32_t)(p * 16 * GST * 4 + st * 32), bb[p]);

#pragma unroll
            for (int mi = 0; mi < 4; mi++)
#pragma unroll
                for (int p = 0; p < 2; p++) {
                    mma_f16(acc[mi][2 * p],     aa[mi], bb[p][0], bb[p][1]);
                    mma_f16(acc[mi][2 * p + 1], aa[mi], bb[p][2], bb[p][3]);
                }
        }
    }

#pragma unroll
    for (int mi = 0; mi < 4; mi++) {
        const int row = bm + wr * 64 + mi * 16 + qr;
#pragma unroll
        for (int ni = 0; ni < 4; ni++) {
            const int col = bn + wc * 32 + ni * 8 + qc * 2;
            const float b0 = bias[col], b1 = bias[col + 1];
            float* d = acc[mi][ni];
            float v00 = d[0] + b0, v01 = d[1] + b1;
            float v10 = d[2] + b0, v11 = d[3] + b1;
            if (MODE == 1) {
                const float sc = (col < DD) ? QSCALE : 1.0f;
                v00 *= sc; v01 *= sc; v10 *= sc; v11 *= sc;
                const int w = col >> 1;
                const int wp = (col < 2 * DD) ? ((w & ~7) | pos8(w & 7)) : w;
                uint32_t* C32 = (uint32_t*)C;
                C32[(size_t)row * (N >> 1) + wp]       = pack_f16x2(v00, v01);
                C32[(size_t)(row + 8) * (N >> 1) + wp] = pack_f16x2(v10, v11);
            } else {
                *(float2*)(C + (size_t)row * N + col)       = make_float2(v00, v01);
                *(float2*)(C + (size_t)(row + 8) * N + col) = make_float2(v10, v11);
            }
        }
    }
}

// ---------------------------------------------------------------------------
// V transpose: qkv V section -> g_vt [(b,h,hd)][seq-pairs], seq-words pos8'd.
// ---------------------------------------------------------------------------
__global__ __launch_bounds__(128) void transpose_v_kernel(
    const float* __restrict__ qkvf, uint32_t* __restrict__ vt)
{
    __shared__ uint32_t ts[64][33];
    const int bh = blockIdx.x;
    const int b = bh >> 4, h = bh & 15;
    const int sc = blockIdx.y;
    const int tid = threadIdx.x;

    const uint32_t* vg = (const uint32_t*)qkvf
        + ((size_t)(b * LL + sc * 64)) * 1536 + 1024 + h * 32;
#pragma unroll
    for (int i = 0; i < 16; i++) {
        const int q = i * 128 + tid;
        const int r = q >> 5, c = q & 31;
        ts[r][c] = vg[(size_t)r * 1536 + c];
    }
    __syncthreads();

#pragma unroll
    for (int i = 0; i < 16; i++) {
        const int q = i * 128 + tid;
        const int hd = q >> 5, sw = q & 31;
        const uint32_t w0 = ts[2 * sw][hd >> 1];
        const uint32_t w1 = ts[2 * sw + 1][hd >> 1];
        const uint32_t sh = (hd & 1) * 16;
        const uint32_t val = ((w0 >> sh) & 0xffffu) | (((w1 >> sh) & 0xffffu) << 16);
        const int swp = (sw & ~7) | pos8(sw & 7);
        vt[((size_t)(bh * 64 + hd)) * (LL / 2) + sc * 32 + swp] = val;
    }
}

// ---------------------------------------------------------------------------
// Causal flash attention, fp16 mma (R13/R14 verbatim; epilogue linear).
// ---------------------------------------------------------------------------
#define AST 40
#define TILE_WORDS (64 * AST)
#define OFF_K0 0
#define OFF_V0 (2 * TILE_WORDS)
#define SMEM_ATTN (4 * TILE_WORDS * 4)   // 40 KB

__global__ __launch_bounds__(128) void attn_f16_kernel(
    const float* __restrict__ qkvf, const uint32_t* __restrict__ vt,
    float* __restrict__ outf)
{
    extern __shared__ uint32_t sm[];
    const uint32_t* qkv = (const uint32_t*)qkvf;
    uint32_t* att = (uint32_t*)outf;

    const int qt = gridDim.x - 1 - blockIdx.x;
    const int h  = blockIdx.y;
    const int b  = blockIdx.z;

    const int tid = threadIdx.x;
    const int lane = tid & 31;
    const int wid = tid >> 5;
    const int qr = lane >> 2;
    const int qc = lane & 3;

    const uint32_t sm_base = (uint32_t)__cvta_generic_to_shared(sm);

    uint32_t qa[2][4][4];
    const uint32_t* qb = qkv + ((size_t)(b * LL + qt * 128 + wid * 32)) * 1536 + h * 32;
#pragma unroll
    for (int mi = 0; mi < 2; mi++)
#pragma unroll
        for (int ks = 0; ks < 4; ks++) {
            const size_t r0 = (size_t)(mi * 16 + qr) * 1536;
            const uint2 u0 = *(const uint2*)(qb + r0 + ks * 8 + 2 * qc);
            const uint2 u1 = *(const uint2*)(qb + r0 + 8 * 1536 + ks * 8 + 2 * qc);
            qa[mi][ks][0] = u0.x; qa[mi][ks][1] = u1.x;
            qa[mi][ks][2] = u0.y; qa[mi][ks][3] = u1.y;
        }

    float o[2][8][4];
    float m[2][2], l[2][2];
#pragma unroll
    for (int mi = 0; mi < 2; mi++) {
        m[mi][0] = m[mi][1] = -INFINITY;
        l[mi][0] = l[mi][1] = 0.0f;
#pragma unroll
        for (int j = 0; j < 8; j++)
#pragma unroll
            for (int c = 0; c < 4; c++) o[mi][j][c] = 0.0f;
    }

    const int jmax = 2 * qt + 1;
    const uint32_t* vtb = vt + ((size_t)((b * HH + h) * 64)) * (LL / 2);

    auto stage = [&](int jt, int s) {
        const uint32_t* kg = qkv + ((size_t)(b * LL + jt * 64)) * 1536 + 512 + h * 32;
#pragma unroll
        for (int i = 0; i < 4; i++) {
            const int q = i * 128 + tid;
            const int r = q >> 3, c = q & 7;
            cp_async16(sm_base + (uint32_t)((OFF_K0 + s * TILE_WORDS + r * AST + c * 4) * 4),
                       kg + (size_t)r * 1536 + c * 4);
        }
#pragma unroll
        for (int i = 0; i < 4; i++) {
            const int q = i * 128 + tid;
            const int r = q >> 3, c = q & 7;
            cp_async16(sm_base + (uint32_t)((OFF_V0 + s * TILE_WORDS + r * AST + c * 4) * 4),
                       vtb + (size_t)r * (LL / 2) + jt * 32 + c * 4);
        }
        cp_commit();
    };

    stage(0, 0);

    for (int jt = 0; jt <= jmax; jt++) {
        const int s = jt & 1;
        __syncthreads();
        if (jt + 1 <= jmax) { stage(jt + 1, s ^ 1); cp_wait<1>(); }
        else                { cp_wait<0>(); }
        __syncthreads();

        const uint32_t* Ks = sm + OFF_K0 + s * TILE_WORDS;
        const uint32_t* Vs = sm + OFF_V0 + s * TILE_WORDS;

        const int wrow_min = qt * 128 + wid * 32;
        const bool tile_dead = (jt * 64) > (wrow_min + 31);

        if (!tile_dead) {
            float sreg[2][8][4];
#pragma unroll
            for (int mi = 0; mi < 2; mi++)
#pragma unroll
                for (int j = 0; j < 8; j++)
#pragma unroll
                    for (int c = 0; c < 4; c++) sreg[mi][j][c] = 0.0f;

#pragma unroll
            for (int ks = 0; ks < 4; ks++) {
#pragma unroll
                for (int j = 0; j < 8; j++) {
                    const uint2 kk = *(const uint2*)&Ks[(j * 8 + qr) * AST + ks * 8 + 2 * qc];
                    mma_f16(sreg[0][j], qa[0][ks], kk.x, kk.y);
                    mma_f16(sreg[1][j], qa[1][ks], kk.x, kk.y);
                }
            }

            if ((jt + 1) * 64 - 1 > wrow_min) {
#pragma unroll
                for (int mi = 0; mi < 2; mi++) {
                    const int r0 = wrow_min + mi * 16 + qr;
#pragma unroll
                    for (int j = 0; j < 8; j++) {
                        const int c0 = jt * 64 + j * 8 + qc * 2;
                        if (c0     > r0)     sreg[mi][j][0] = -INFINITY;
                        if (c0 + 1 > r0)     sreg[mi][j][1] = -INFINITY;
                        if (c0     > r0 + 8) sreg[mi][j][2] = -INFINITY;
                        if (c0 + 1 > r0 + 8) sreg[mi][j][3] = -INFINITY;
                    }
                }
            }

#pragma unroll
            for (int mi = 0; mi < 2; mi++) {
                float mt0 = -INFINITY, mt1 = -INFINITY;
#pragma unroll
                for (int j = 0; j < 8; j++) {
                    mt0 = fmaxf(mt0, fmaxf(sreg[mi][j][0], sreg[mi][j][1]));
                    mt1 = fmaxf(mt1, fmaxf(sreg[mi][j][2], sreg[mi][j][3]));
                }
#pragma unroll
                for (int off = 1; off <= 2; off <<= 1) {
                    mt0 = fmaxf(mt0, __shfl_xor_sync(0xffffffffu, mt0, off));
                    mt1 = fmaxf(mt1, __shfl_xor_sync(0xffffffffu, mt1, off));
                }
                const float mn0 = fmaxf(m[mi][0], mt0);
                const float mn1 = fmaxf(m[mi][1], mt1);
                const float al0 = exp2f(m[mi][0] - mn0);
                const float al1 = exp2f(m[mi][1] - mn1);
                m[mi][0] = mn0; m[mi][1] = mn1;
                float rs0 = 0.0f, rs1 = 0.0f;
#pragma unroll
                for (int j = 0; j < 8; j++) {
                    sreg[mi][j][0] = exp2f(sreg[mi][j][0] - mn0);
                    sreg[mi][j][1] = exp2f(sreg[mi][j][1] - mn0);
                    sreg[mi][j][2] = exp2f(sreg[mi][j][2] - mn1);
                    sreg[mi][j][3] = exp2f(sreg[mi][j][3] - mn1);
                    rs0 += sreg[mi][j][0] + sreg[mi][j][1];
                    rs1 += sreg[mi][j][2] + sreg[mi][j][3];
                }
#pragma unroll
                for (int off = 1; off <= 2; off <<= 1) {
                    rs0 += __shfl_xor_sync(0xffffffffu, rs0, off);
                    rs1 += __shfl_xor_sync(0xffffffffu, rs1, off);
                }
                l[mi][0] = l[mi][0] * al0 + rs0;
                l[mi][1] = l[mi][1] * al1 + rs1;
#pragma unroll
                for (int j = 0; j < 8; j++) {
                    o[mi][j][0] *= al0; o[mi][j][1] *= al0;
                    o[mi][j][2] *= al1; o[mi][j][3] *= al1;
                }
            }

#pragma unroll
            for (int ks = 0; ks < 4; ks++) {
                uint32_t pa0[4], pa1[4];
                pa0[0] = pack_f16x2(sreg[0][2 * ks][0],     sreg[0][2 * ks][1]);
                pa0[1] = pack_f16x2(sreg[0][2 * ks][2],     sreg[0][2 * ks][3]);
                pa0[2] = pack_f16x2(sreg[0][2 * ks + 1][0], sreg[0][2 * ks + 1][1]);
                pa0[3] = pack_f16x2(sreg[0][2 * ks + 1][2], sreg[0][2 * ks + 1][3]);
                pa1[0] = pack_f16x2(sreg[1][2 * ks][0],     sreg[1][2 * ks][1]);
                pa1[1] = pack_f16x2(sreg[1][2 * ks][2],     sreg[1][2 * ks][3]);
                pa1[2] = pack_f16x2(sreg[1][2 * ks + 1][0], sreg[1][2 * ks + 1][1]);
                pa1[3] = pack_f16x2(sreg[1][2 * ks + 1][2], sreg[1][2 * ks + 1][3]);
#pragma unroll
                for (int j = 0; j < 8; j++) {
                    const uint2 vv = *(const uint2*)&Vs[(j * 8 + qr) * AST + ks * 8 + 2 * qc];
                    mma_f16(o[0][j], pa0, vv.x, vv.y);
                    mma_f16(o[1][j], pa1, vv.x, vv.y);
                }
            }
        }
    }

    // epilogue: LINEAR word layout (GEMM0 uses ldmatrix)
    const int orow0 = b * LL + qt * 128 + wid * 32;
#pragma unroll
    for (int mi = 0; mi < 2; mi++) {
        const float inv0 = 1.0f / l[mi][0];
        const float inv1 = 1.0f / l[mi][1];
        const size_t r0 = (size_t)(orow0 + mi * 16 + qr) * 512;
#pragma unroll
        for (int j = 0; j < 8; j++) {
            const int wp = h * 32 + j * 4 + qc;
            att[r0 + wp]           = pack_f16x2(o[mi][j][0] * inv0, o[mi][j][1] * inv0);
            att[r0 + 8 * 512 + wp] = pack_f16x2(o[mi][j][2] * inv1, o[mi][j][3] * inv1);
        }
    }
}

// ---------------------------------------------------------------------------
extern "C" void kernel_launch(void* const* d_in, const int* in_sizes, int n_in,
                              void* d_out, int out_size)
{
    const float* x    = (const float*)d_in[0];
    const float* Wqkv = (const float*)d_in[1];
    const float* bqkv = (const float*)d_in[2];
    const float* Wout = (const float*)d_in[3];
    const float* bout = (const float*)d_in[4];
    float* outp = (float*)d_out;

    float *qkv = nullptr, *att = nullptr;
    uint32_t *xt = nullptr, *wq = nullptr, *wo = nullptr, *vt = nullptr;
    cudaGetSymbolAddress((void**)&qkv, g_qkv);
    cudaGetSymbolAddress((void**)&att, g_att);
    cudaGetSymbolAddress((void**)&xt, g_xt);
    cudaGetSymbolAddress((void**)&wq, g_wq);
    cudaGetSymbolAddress((void**)&wo, g_wo);
    cudaGetSymbolAddress((void**)&vt, g_vt);

    static bool attr_set = false;
    if (!attr_set) {
        cudaFuncSetAttribute(attn_f16_kernel,
                             cudaFuncAttributeMaxDynamicSharedMemorySize, SMEM_ATTN);
        cudaFuncSetAttribute(gemm_f16<0>,
                             cudaFuncAttributeMaxDynamicSharedMemorySize, SMEM_GEMM);
        cudaFuncSetAttribute(gemm_f16<1>,
                             cudaFuncAttributeMaxDynamicSharedMemorySize, SMEM_GEMM);
        attr_set = true;
    }

    const int M = BB * LL;   // 8192
    const int Kw = DD / 2;   // 512 words

    // prepass: plain fp32 -> fp16 (linear; ldmatrix handles lane distribution)
    {
        int n8 = (M * DD) / 8;
        conv_f16_kernel<<<(n8 + 255) / 256, 256>>>(x, xt, n8);
        n8 = (3 * DD * DD) / 8;
        conv_f16_kernel<<<(n8 + 255) / 256, 256>>>(Wqkv, wq, n8);
        n8 = (DD * DD) / 8;
        conv_f16_kernel<<<(n8 + 255) / 256, 256>>>(Wout, wo, n8);
    }

    // 1) QKV projection (fp16 words out; Q scaled; Q/K pos8, V linear)
    {
        dim3 grid((3 * DD) / 128, M / 128);
        gemm_f16<1><<<grid, 256, SMEM_GEMM>>>(xt, wq, bqkv, qkv, M, 3 * DD, Kw);
    }

    // 1b) V transpose -> [(b,h,hd)][seq-pairs]
    {
        dim3 grid(BB * HH, LL / 64);
        transpose_v_kernel<<<grid, 128>>>(qkv, vt);
    }

    // 2) causal attention (att written linear)
    {
        dim3 grid(LL / 128, HH, BB);
        attn_f16_kernel<<<grid, 128, SMEM_ATTN>>>(qkv, vt, att);
    }

    // 3) output projection (fp32 out)
    {
        dim3 grid(DD / 128, M / 128);
        gemm_f16<0><<<grid, 256, SMEM_GEMM>>>((const uint32_t*)att, wo, bout, outp,
                                              M, DD, Kw);
    }
}

// round 16
// speedup vs baseline: 1.0105x; 1.0105x over previous
#include <cuda_runtime.h>
#include <math.h>
#include <stdint.h>

#define BB 4
#define LL 2048
#define DD 1024
#define HH 16
#define HD 64

// Q prescale: 1/sqrt(64) * log2(e) -> softmax in exp2 domain.
#define QSCALE 0.1803368801111204f

// Scratch (device globals). All fp16 payloads stored as packed uint32 words.
// ALL layouts linear now (ldmatrix handles lane distribution everywhere).
__device__ float    g_qkv[(size_t)BB * LL * 3 * DD];       // fp16 words [M][1536]
__device__ float    g_att[(size_t)BB * LL * DD];           // fp16 words [M][512]
__device__ uint32_t g_xt  [(size_t)BB * LL * DD];          // x fp16 words
__device__ uint32_t g_wq  [(size_t)3 * DD * DD];           // Wqkv fp16 words
__device__ uint32_t g_wo  [(size_t)DD * DD];               // Wout fp16 words
__device__ uint32_t g_vt  [(size_t)BB * HH * HD * (LL/2)]; // V^T fp16 words [(b,h,hd)][1024]

__device__ __forceinline__ uint32_t pack_f16x2(float lo, float hi) {
    uint32_t r;
    asm("cvt.rn.f16x2.f32 %0, %1, %2;" : "=r"(r) : "f"(hi), "f"(lo));
    return r;
}

__device__ __forceinline__ void cp_async16(uint32_t smem_addr, const void* gptr) {
    asm volatile("cp.async.cg.shared.global [%0], [%1], 16;\n"
                 :: "r"(smem_addr), "l"(gptr));
}
__device__ __forceinline__ void cp_commit() {
    asm volatile("cp.async.commit_group;\n" ::: "memory");
}
template <int N>
__device__ __forceinline__ void cp_wait() {
    asm volatile("cp.async.wait_group %0;\n" :: "n"(N) : "memory");
}

// m16n8k16 f16 mma, f32 acc.
__device__ __forceinline__ void mma_f16(float* d, const uint32_t* a,
                                        uint32_t b0, uint32_t b1) {
    asm volatile(
        "mma.sync.aligned.m16n8k16.row.col.f32.f16.f16.f32 "
        "{%0,%1,%2,%3}, {%4,%5,%6,%7}, {%8,%9}, {%0,%1,%2,%3};\n"
        : "+f"(d[0]), "+f"(d[1]), "+f"(d[2]), "+f"(d[3])
        : "r"(a[0]), "r"(a[1]), "r"(a[2]), "r"(a[3]), "r"(b0), "r"(b1));
}

// ldmatrix x4 (non-transposed), b16.
__device__ __forceinline__ void ldsm_x4(uint32_t addr, uint32_t* r) {
    asm volatile("ldmatrix.sync.aligned.m8n8.x4.shared.b16 {%0,%1,%2,%3}, [%4];"
                 : "=r"(r[0]), "=r"(r[1]), "=r"(r[2]), "=r"(r[3]) : "r"(addr));
}

// ---------------------------------------------------------------------------
// Prepass: fp32 -> fp16 words (linear layout).
// ---------------------------------------------------------------------------
__global__ void conv_f16_kernel(const float* __restrict__ in,
                                uint32_t* __restrict__ out, int n8) {
    int i = blockIdx.x * blockDim.x + threadIdx.x;
    if (i >= n8) return;
    const float4 v0 = *(const float4*)(in + (size_t)i * 8);
    const float4 v1 = *(const float4*)(in + (size_t)i * 8 + 4);
    uint4 r;
    r.x = pack_f16x2(v0.x, v0.y);
    r.y = pack_f16x2(v0.z, v0.w);
    r.z = pack_f16x2(v1.x, v1.y);
    r.w = pack_f16x2(v1.z, v1.w);
    *(uint4*)(out + (size_t)i * 4) = r;
}

// ---------------------------------------------------------------------------
// fp16 GEMM (mma.sync m16n8k16 + ldmatrix) — R14 config (best measured):
// block 128x64, 4 warps (2x2), warp 64x32 (acc=64 regs), kTile 32 words,
// 2-stage cp.async, stride-36 rows (LDSM + cp.async phases conflict-free),
// launch_bounds(128,4) -> 4 CTAs/SM.
// MODE 0: fp32 out + bias. MODE 1: fp16 out, Q cols scaled by QSCALE (linear).
// ---------------------------------------------------------------------------
#define GST 36
#define ABW (128 * GST)                  // A words per stage
#define WBW (64 * GST)                   // W words per stage
#define STGW (ABW + WBW)                 // 6912 words per stage
#define SMEM_GEMM (2 * STGW * 4)         // 55296 B

template <int MODE>
__global__ __launch_bounds__(128, 4) void gemm_f16(
    const uint32_t* __restrict__ A, const uint32_t* __restrict__ W,
    const float* __restrict__ bias, float* __restrict__ C,
    int M, int N, int Kw)
{
    extern __shared__ uint32_t gsm[];

    const int tid = threadIdx.x;
    const int lane = tid & 31;
    const int ww = tid >> 5;
    const int wr = ww >> 1;          // 0..1 (64-row band)
    const int wc = ww & 1;           // 0..1 (32-col band)
    const int qr = lane >> 2;
    const int qc = lane & 3;
    const int bm = blockIdx.y * 128;
    const int bn = blockIdx.x * 64;

    float acc[4][4][4];
#pragma unroll
    for (int i = 0; i < 4; i++)
#pragma unroll
        for (int j = 0; j < 4; j++)
#pragma unroll
            for (int c = 0; c < 4; c++) acc[i][j][c] = 0.0f;

    const uint32_t sm_base = (uint32_t)__cvta_generic_to_shared(gsm);
    const int nkt = Kw / 32;

    const uint32_t a_lane = (uint32_t)(((wr * 64 + (lane & 15)) * GST
                                        + (lane >> 4) * 4) * 4);
    const uint32_t b_lane = (uint32_t)(((wc * 32 + ((lane >> 4) << 3) + (lane & 7)) * GST
                                        + ((lane >> 3) & 1) * 4) * 4);

    auto stage = [&](int kt_idx, int s) {
#pragma unroll
        for (int i = 0; i < 8; i++) {       // A: 1024 chunks of 16B
            const int q = i * 128 + tid;
            const int r = q >> 3, c = q & 7;
            cp_async16(sm_base + (uint32_t)((s * STGW + r * GST + c * 4) * 4),
                       A + (size_t)(bm + r) * Kw + kt_idx * 32 + c * 4);
        }
#pragma unroll
        for (int i = 0; i < 4; i++) {       // W: 512 chunks
            const int q = i * 128 + tid;
            const int r = q >> 3, c = q & 7;
            cp_async16(sm_base + (uint32_t)((s * STGW + ABW + r * GST + c * 4) * 4),
                       W + (size_t)(bn + r) * Kw + kt_idx * 32 + c * 4);
        }
        cp_commit();
    };

    stage(0, 0);

    for (int kt = 0; kt < nkt; kt++) {
        const int s = kt & 1;
        __syncthreads();
        if (kt + 1 < nkt) { stage(kt + 1, s ^ 1); cp_wait<1>(); }
        else              { cp_wait<0>(); }
        __syncthreads();

        const uint32_t abase = sm_base + (uint32_t)(s * STGW * 4) + a_lane;
        const uint32_t bbase = sm_base + (uint32_t)((s * STGW + ABW) * 4) + b_lane;

#pragma unroll
        for (int st = 0; st < 4; st++) {
            uint32_t aa[4][4], bb[2][4];
#pragma unroll
            for (int mi = 0; mi < 4; mi++)
                ldsm_x4(abase + (uint32_t)(mi * 16 * GST * 4 + st * 32), aa[mi]);
#pragma unroll
            for (int p = 0; p < 2; p++)
                ldsm_x4(bbase + (uint32_t)(p * 16 * GST * 4 + st * 32), bb[p]);

#pragma unroll
            for (int mi = 0; mi < 4; mi++)
#pragma unroll
                for (int p = 0; p < 2; p++) {
                    mma_f16(acc[mi][2 * p],     aa[mi], bb[p][0], bb[p][1]);
                    mma_f16(acc[mi][2 * p + 1], aa[mi], bb[p][2], bb[p][3]);
                }
        }
    }

#pragma unroll
    for (int mi = 0; mi < 4; mi++) {
        const int row = bm + wr * 64 + mi * 16 + qr;
#pragma unroll
        for (int ni = 0; ni < 4; ni++) {
            const int col = bn + wc * 32 + ni * 8 + qc * 2;
            const float b0 = bias[col], b1 = bias[col + 1];
            float* d = acc[mi][ni];
            float v00 = d[0] + b0, v01 = d[1] + b1;
            float v10 = d[2] + b0, v11 = d[3] + b1;
            if (MODE == 1) {
                const float sc = (col < DD) ? QSCALE : 1.0f;
                v00 *= sc; v01 *= sc; v10 *= sc; v11 *= sc;
                const int w = col >> 1;
                uint32_t* C32 = (uint32_t*)C;
                C32[(size_t)row * (N >> 1) + w]       = pack_f16x2(v00, v01);
                C32[(size_t)(row + 8) * (N >> 1) + w] = pack_f16x2(v10, v11);
            } else {
                *(float2*)(C + (size_t)row * N + col)       = make_float2(v00, v01);
                *(float2*)(C + (size_t)(row + 8) * N + col) = make_float2(v10, v11);
            }
        }
    }
}

// ---------------------------------------------------------------------------
// V transpose: qkv V section -> g_vt [(b,h,hd)][seq-pairs], LINEAR seq words.
// ---------------------------------------------------------------------------
__global__ __launch_bounds__(128) void transpose_v_kernel(
    const float* __restrict__ qkvf, uint32_t* __restrict__ vt)
{
    __shared__ uint32_t ts[64][33];
    const int bh = blockIdx.x;
    const int b = bh >> 4, h = bh & 15;
    const int sc = blockIdx.y;
    const int tid = threadIdx.x;

    const uint32_t* vg = (const uint32_t*)qkvf
        + ((size_t)(b * LL + sc * 64)) * 1536 + 1024 + h * 32;
#pragma unroll
    for (int i = 0; i < 16; i++) {
        const int q = i * 128 + tid;
        const int r = q >> 5, c = q & 31;
        ts[r][c] = vg[(size_t)r * 1536 + c];
    }
    __syncthreads();

#pragma unroll
    for (int i = 0; i < 16; i++) {
        const int q = i * 128 + tid;
        const int hd = q >> 5, sw = q & 31;
        const uint32_t w0 = ts[2 * sw][hd >> 1];
        const uint32_t w1 = ts[2 * sw + 1][hd >> 1];
        const uint32_t sh = (hd & 1) * 16;
        const uint32_t val = ((w0 >> sh) & 0xffffu) | (((w1 >> sh) & 0xffffu) << 16);
        vt[((size_t)(bh * 64 + hd)) * (LL / 2) + sc * 32 + sw] = val;
    }
}

// ---------------------------------------------------------------------------
// Causal flash attention, fp16 mma + LDSM fragment feed.
// Grid (L/128, H, B) qt reversed, 4 warps, warp owns 32 q rows.
// K smem [seq][hd-words] stride 36; Vt smem [hd][seq-words] stride 36;
// both LINEAR — B fragments via ldmatrix.x4 (16 per tile per operand-pass).
// Q fragments gathered from linear global once. P packed from registers.
// ---------------------------------------------------------------------------
#define AST 36
#define TILE_WORDS (64 * AST)
#define OFF_K0 0
#define OFF_V0 (2 * TILE_WORDS)
#define SMEM_ATTN (4 * TILE_WORDS * 4)   // 36864 B

__global__ __launch_bounds__(128) void attn_f16_kernel(
    const float* __restrict__ qkvf, const uint32_t* __restrict__ vt,
    float* __restrict__ outf)
{
    extern __shared__ uint32_t sm[];
    const uint32_t* qkv = (const uint32_t*)qkvf;
    uint32_t* att = (uint32_t*)outf;

    const int qt = gridDim.x - 1 - blockIdx.x;
    const int h  = blockIdx.y;
    const int b  = blockIdx.z;

    const int tid = threadIdx.x;
    const int lane = tid & 31;
    const int wid = tid >> 5;
    const int qr = lane >> 2;
    const int qc = lane & 3;

    const uint32_t sm_base = (uint32_t)__cvta_generic_to_shared(sm);

    // ldmatrix B-operand lane offset (same convention as GEMM, stride AST):
    const uint32_t bl_lane = (uint32_t)(((((lane >> 4) << 3) + (lane & 7)) * AST
                                         + ((lane >> 3) & 1) * 4) * 4);

    // Q fragments from linear global (a0: k=2qc @word qc; a2: k=2qc+8 @word qc+4)
    uint32_t qa[2][4][4];
    const uint32_t* qb = qkv + ((size_t)(b * LL + qt * 128 + wid * 32)) * 1536 + h * 32;
#pragma unroll
    for (int mi = 0; mi < 2; mi++)
#pragma unroll
        for (int ks = 0; ks < 4; ks++) {
            const size_t r0 = (size_t)(mi * 16 + qr) * 1536;
            qa[mi][ks][0] = qb[r0 + ks * 8 + qc];
            qa[mi][ks][1] = qb[r0 + 8 * 1536 + ks * 8 + qc];
            qa[mi][ks][2] = qb[r0 + ks * 8 + 4 + qc];
            qa[mi][ks][3] = qb[r0 + 8 * 1536 + ks * 8 + 4 + qc];
        }

    float o[2][8][4];
    float m[2][2], l[2][2];
#pragma unroll
    for (int mi = 0; mi < 2; mi++) {
        m[mi][0] = m[mi][1] = -INFINITY;
        l[mi][0] = l[mi][1] = 0.0f;
#pragma unroll
        for (int j = 0; j < 8; j++)
#pragma unroll
            for (int c = 0; c < 4; c++) o[mi][j][c] = 0.0f;
    }

    const int jmax = 2 * qt + 1;
    const uint32_t* vtb = vt + ((size_t)((b * HH + h) * 64)) * (LL / 2);

    auto stage = [&](int jt, int s) {
        const uint32_t* kg = qkv + ((size_t)(b * LL + jt * 64)) * 1536 + 512 + h * 32;
#pragma unroll
        for (int i = 0; i < 4; i++) {
            const int q = i * 128 + tid;
            const int r = q >> 3, c = q & 7;
            cp_async16(sm_base + (uint32_t)((OFF_K0 + s * TILE_WORDS + r * AST + c * 4) * 4),
                       kg + (size_t)r * 1536 + c * 4);
        }
#pragma unroll
        for (int i = 0; i < 4; i++) {
            const int q = i * 128 + tid;
            const int r = q >> 3, c = q & 7;
            cp_async16(sm_base + (uint32_t)((OFF_V0 + s * TILE_WORDS + r * AST + c * 4) * 4),
                       vtb + (size_t)r * (LL / 2) + jt * 32 + c * 4);
        }
        cp_commit();
    };

    stage(0, 0);

    for (int jt = 0; jt <= jmax; jt++) {
        const int s = jt & 1;
        __syncthreads();
        if (jt + 1 <= jmax) { stage(jt + 1, s ^ 1); cp_wait<1>(); }
        else                { cp_wait<0>(); }
        __syncthreads();

        const uint32_t kbase = sm_base + (uint32_t)((OFF_K0 + s * TILE_WORDS) * 4) + bl_lane;
        const uint32_t vbase = sm_base + (uint32_t)((OFF_V0 + s * TILE_WORDS) * 4) + bl_lane;

        const int wrow_min = qt * 128 + wid * 32;
        const bool tile_dead = (jt * 64) > (wrow_min + 31);

        if (!tile_dead) {
            // S = Q K^T  (K B-fragments via LDSM)
            float sreg[2][8][4];
#pragma unroll
            for (int mi = 0; mi < 2; mi++)
#pragma unroll
                for (int j = 0; j < 8; j++)
#pragma unroll
                    for (int c = 0; c < 4; c++) sreg[mi][j][c] = 0.0f;

#pragma unroll
            for (int jj = 0; jj < 4; jj++) {        // 16 seq rows per jj
#pragma unroll
                for (int ks = 0; ks < 4; ks++) {
                    uint32_t kb[4];
                    ldsm_x4(kbase + (uint32_t)(jj * 16 * AST * 4 + ks * 32), kb);
                    mma_f16(sreg[0][2 * jj],     qa[0][ks], kb[0], kb[1]);
                    mma_f16(sreg[1][2 * jj],     qa[1][ks], kb[0], kb[1]);
                    mma_f16(sreg[0][2 * jj + 1], qa[0][ks], kb[2], kb[3]);
                    mma_f16(sreg[1][2 * jj + 1], qa[1][ks], kb[2], kb[3]);
                }
            }

            // causal mask
            if ((jt + 1) * 64 - 1 > wrow_min) {
#pragma unroll
                for (int mi = 0; mi < 2; mi++) {
                    const int r0 = wrow_min + mi * 16 + qr;
#pragma unroll
                    for (int j = 0; j < 8; j++) {
                        const int c0 = jt * 64 + j * 8 + qc * 2;
                        if (c0     > r0)     sreg[mi][j][0] = -INFINITY;
                        if (c0 + 1 > r0)     sreg[mi][j][1] = -INFINITY;
                        if (c0     > r0 + 8) sreg[mi][j][2] = -INFINITY;
                        if (c0 + 1 > r0 + 8) sreg[mi][j][3] = -INFINITY;
                    }
                }
            }

            // online softmax (base 2)
#pragma unroll
            for (int mi = 0; mi < 2; mi++) {
                float mt0 = -INFINITY, mt1 = -INFINITY;
#pragma unroll
                for (int j = 0; j < 8; j++) {
                    mt0 = fmaxf(mt0, fmaxf(sreg[mi][j][0], sreg[mi][j][1]));
                    mt1 = fmaxf(mt1, fmaxf(sreg[mi][j][2], sreg[mi][j][3]));
                }
#pragma unroll
                for (int off = 1; off <= 2; off <<= 1) {
                    mt0 = fmaxf(mt0, __shfl_xor_sync(0xffffffffu, mt0, off));
                    mt1 = fmaxf(mt1, __shfl_xor_sync(0xffffffffu, mt1, off));
                }
                const float mn0 = fmaxf(m[mi][0], mt0);
                const float mn1 = fmaxf(m[mi][1], mt1);
                const float al0 = exp2f(m[mi][0] - mn0);
                const float al1 = exp2f(m[mi][1] - mn1);
                m[mi][0] = mn0; m[mi][1] = mn1;
                float rs0 = 0.0f, rs1 = 0.0f;
#pragma unroll
                for (int j = 0; j < 8; j++) {
                    sreg[mi][j][0] = exp2f(sreg[mi][j][0] - mn0);
                    sreg[mi][j][1] = exp2f(sreg[mi][j][1] - mn0);
                    sreg[mi][j][2] = exp2f(sreg[mi][j][2] - mn1);
                    sreg[mi][j][3] = exp2f(sreg[mi][j][3] - mn1);
                    rs0 += sreg[mi][j][0] + sreg[mi][j][1];
                    rs1 += sreg[mi][j][2] + sreg[mi][j][3];
                }
#pragma unroll
                for (int off = 1; off <= 2; off <<= 1) {
                    rs0 += __shfl_xor_sync(0xffffffffu, rs0, off);
                    rs1 += __shfl_xor_sync(0xffffffffu, rs1, off);
                }
                l[mi][0] = l[mi][0] * al0 + rs0;
                l[mi][1] = l[mi][1] * al1 + rs1;
#pragma unroll
                for (int j = 0; j < 8; j++) {
                    o[mi][j][0] *= al0; o[mi][j][1] *= al0;
                    o[mi][j][2] *= al1; o[mi][j][3] *= al1;
                }
            }

            // pack P A-fragments (per ks16 step)
            uint32_t pa[2][4][4];
#pragma unroll
            for (int mi = 0; mi < 2; mi++)
#pragma unroll
                for (int ks = 0; ks < 4; ks++) {
                    pa[mi][ks][0] = pack_f16x2(sreg[mi][2 * ks][0],     sreg[mi][2 * ks][1]);
                    pa[mi][ks][1] = pack_f16x2(sreg[mi][2 * ks][2],     sreg[mi][2 * ks][3]);
                    pa[mi][ks][2] = pack_f16x2(sreg[mi][2 * ks + 1][0], sreg[mi][2 * ks + 1][1]);
                    pa[mi][ks][3] = pack_f16x2(sreg[mi][2 * ks + 1][2], sreg[mi][2 * ks + 1][3]);
                }

            // O += P @ V^T  (Vt B-fragments via LDSM)
#pragma unroll
            for (int jj = 0; jj < 4; jj++) {        // 16 hd rows per jj
#pragma unroll
                for (int ks = 0; ks < 4; ks++) {
                    uint32_t vb[4];
                    ldsm_x4(vbase + (uint32_t)(jj * 16 * AST * 4 + ks * 32), vb);
                    mma_f16(o[0][2 * jj],     pa[0][ks], vb[0], vb[1]);
                    mma_f16(o[1][2 * jj],     pa[1][ks], vb[0], vb[1]);
                    mma_f16(o[0][2 * jj + 1], pa[0][ks], vb[2], vb[3]);
                    mma_f16(o[1][2 * jj + 1], pa[1][ks], vb[2], vb[3]);
                }
            }
        }
    }

    // epilogue: LINEAR word layout
    const int orow0 = b * LL + qt * 128 + wid * 32;
#pragma unroll
    for (int mi = 0; mi < 2; mi++) {
        const float inv0 = 1.0f / l[mi][0];
        const float inv1 = 1.0f / l[mi][1];
        const size_t r0 = (size_t)(orow0 + mi * 16 + qr) * 512;
#pragma unroll
        for (int j = 0; j < 8; j++) {
            const int wp = h * 32 + j * 4 + qc;
            att[r0 + wp]           = pack_f16x2(o[mi][j][0] * inv0, o[mi][j][1] * inv0);
            att[r0 + 8 * 512 + wp] = pack_f16x2(o[mi][j][2] * inv1, o[mi][j][3] * inv1);
        }
    }
}

// ---------------------------------------------------------------------------
extern "C" void kernel_launch(void* const* d_in, const int* in_sizes, int n_in,
                              void* d_out, int out_size)
{
    const float* x    = (const float*)d_in[0];
    const float* Wqkv = (const float*)d_in[1];
    const float* bqkv = (const float*)d_in[2];
    const float* Wout = (const float*)d_in[3];
    const float* bout = (const float*)d_in[4];
    float* outp = (float*)d_out;

    float *qkv = nullptr, *att = nullptr;
    uint32_t *xt = nullptr, *wq = nullptr, *wo = nullptr, *vt = nullptr;
    cudaGetSymbolAddress((void**)&qkv, g_qkv);
    cudaGetSymbolAddress((void**)&att, g_att);
    cudaGetSymbolAddress((void**)&xt, g_xt);
    cudaGetSymbolAddress((void**)&wq, g_wq);
    cudaGetSymbolAddress((void**)&wo, g_wo);
    cudaGetSymbolAddress((void**)&vt, g_vt);

    static bool attr_set = false;
    if (!attr_set) {
        cudaFuncSetAttribute(attn_f16_kernel,
                             cudaFuncAttributeMaxDynamicSharedMemorySize, SMEM_ATTN);
        cudaFuncSetAttribute(gemm_f16<0>,
                             cudaFuncAttributeMaxDynamicSharedMemorySize, SMEM_GEMM);
        cudaFuncSetAttribute(gemm_f16<1>,
                             cudaFuncAttributeMaxDynamicSharedMemorySize, SMEM_GEMM);
        attr_set = true;
    }

    const int M = BB * LL;   // 8192
    const int Kw = DD / 2;   // 512 words

    // prepass: plain fp32 -> fp16 (linear everywhere)
    {
        int n8 = (M * DD) / 8;
        conv_f16_kernel<<<(n8 + 255) / 256, 256>>>(x, xt, n8);
        n8 = (3 * DD * DD) / 8;
        conv_f16_kernel<<<(n8 + 255) / 256, 256>>>(Wqkv, wq, n8);
        n8 = (DD * DD) / 8;
        conv_f16_kernel<<<(n8 + 255) / 256, 256>>>(Wout, wo, n8);
    }

    // 1) QKV projection (fp16 words out; Q scaled; all linear)
    {
        dim3 grid((3 * DD) / 64, M / 128);
        gemm_f16<1><<<grid, 128, SMEM_GEMM>>>(xt, wq, bqkv, qkv, M, 3 * DD, Kw);
    }

    // 1b) V transpose -> [(b,h,hd)][seq-pairs], linear
    {
        dim3 grid(BB * HH, LL / 64);
        transpose_v_kernel<<<grid, 128>>>(qkv, vt);
    }

    // 2) causal attention
    {
        dim3 grid(LL / 128, HH, BB);
        attn_f16_kernel<<<grid, 128, SMEM_ATTN>>>(qkv, vt, att);
    }

    // 3) output projection (fp32 out)
    {
        dim3 grid(DD / 64, M / 128);
        gemm_f16<0><<<grid, 128, SMEM_GEMM>>>((const uint32_t*)att, wo, bout, outp,
                                              M, DD, Kw);
    }
}

// round 17
// speedup vs baseline: 1.0561x; 1.0451x over previous
#include <cuda_runtime.h>
#include <math.h>
#include <stdint.h>

#define BB 4
#define LL 2048
#define DD 1024
#define HH 16
#define HD 64

// Q prescale: 1/sqrt(64) * log2(e) -> softmax in exp2 domain.
#define QSCALE 0.1803368801111204f

// Scratch (device globals). All fp16 payloads stored as packed uint32 words.
// ALL layouts linear (ldmatrix handles lane distribution everywhere).
__device__ float    g_qkv[(size_t)BB * LL * 3 * DD];       // fp16 words [M][1536]
__device__ float    g_att[(size_t)BB * LL * DD];           // fp16 words [M][512]
__device__ uint32_t g_xt  [(size_t)BB * LL * DD];          // x fp16 words
__device__ uint32_t g_wq  [(size_t)3 * DD * DD];           // Wqkv fp16 words
__device__ uint32_t g_wo  [(size_t)DD * DD];               // Wout fp16 words

__device__ __forceinline__ uint32_t pack_f16x2(float lo, float hi) {
    uint32_t r;
    asm("cvt.rn.f16x2.f32 %0, %1, %2;" : "=r"(r) : "f"(hi), "f"(lo));
    return r;
}

__device__ __forceinline__ void cp_async16(uint32_t smem_addr, const void* gptr) {
    asm volatile("cp.async.cg.shared.global [%0], [%1], 16;\n"
                 :: "r"(smem_addr), "l"(gptr));
}
__device__ __forceinline__ void cp_commit() {
    asm volatile("cp.async.commit_group;\n" ::: "memory");
}
template <int N>
__device__ __forceinline__ void cp_wait() {
    asm volatile("cp.async.wait_group %0;\n" :: "n"(N) : "memory");
}

// m16n8k16 f16 mma, f32 acc.
__device__ __forceinline__ void mma_f16(float* d, const uint32_t* a,
                                        uint32_t b0, uint32_t b1) {
    asm volatile(
        "mma.sync.aligned.m16n8k16.row.col.f32.f16.f16.f32 "
        "{%0,%1,%2,%3}, {%4,%5,%6,%7}, {%8,%9}, {%0,%1,%2,%3};\n"
        : "+f"(d[0]), "+f"(d[1]), "+f"(d[2]), "+f"(d[3])
        : "r"(a[0]), "r"(a[1]), "r"(a[2]), "r"(a[3]), "r"(b0), "r"(b1));
}

// ldmatrix x4 (non-transposed), b16.
__device__ __forceinline__ void ldsm_x4(uint32_t addr, uint32_t* r) {
    asm volatile("ldmatrix.sync.aligned.m8n8.x4.shared.b16 {%0,%1,%2,%3}, [%4];"
                 : "=r"(r[0]), "=r"(r[1]), "=r"(r[2]), "=r"(r[3]) : "r"(addr));
}
// ldmatrix x4 transposed, b16 (HW transpose: feeds B-operand from [k][n] memory).
__device__ __forceinline__ void ldsm_x4_t(uint32_t addr, uint32_t* r) {
    asm volatile("ldmatrix.sync.aligned.m8n8.x4.trans.shared.b16 {%0,%1,%2,%3}, [%4];"
                 : "=r"(r[0]), "=r"(r[1]), "=r"(r[2]), "=r"(r[3]) : "r"(addr));
}

// ---------------------------------------------------------------------------
// Prepass (single launch): fp32 -> fp16 words for x, Wqkv, Wout.
// ---------------------------------------------------------------------------
__global__ void conv_f16_all(const float* __restrict__ x,   uint32_t* __restrict__ xo,
                             const float* __restrict__ w1,  uint32_t* __restrict__ w1o,
                             const float* __restrict__ w2,  uint32_t* __restrict__ w2o,
                             int n1, int n2, int n3) {
    int i = blockIdx.x * blockDim.x + threadIdx.x;
    const float* in;
    uint32_t* out;
    if (i < n1)            { in = x;  out = xo; }
    else if (i < n1 + n2)  { i -= n1; in = w1; out = w1o; }
    else if (i < n1 + n2 + n3) { i -= n1 + n2; in = w2; out = w2o; }
    else return;
    const float4 v0 = *(const float4*)(in + (size_t)i * 8);
    const float4 v1 = *(const float4*)(in + (size_t)i * 8 + 4);
    uint4 r;
    r.x = pack_f16x2(v0.x, v0.y);
    r.y = pack_f16x2(v0.z, v0.w);
    r.z = pack_f16x2(v1.x, v1.y);
    r.w = pack_f16x2(v1.z, v1.w);
    *(uint4*)(out + (size_t)i * 4) = r;
}

// ---------------------------------------------------------------------------
// fp16 GEMM (mma.sync m16n8k16 + ldmatrix) — R14 config (best measured):
// block 128x64, 4 warps (2x2), warp 64x32 (acc=64 regs), kTile 32 words,
// 2-stage cp.async, stride-36 rows (LDSM + cp.async phases conflict-free),
// launch_bounds(128,4) -> 4 CTAs/SM.
// MODE 0: fp32 out + bias. MODE 1: fp16 out, Q cols scaled by QSCALE (linear).
// ---------------------------------------------------------------------------
#define GST 36
#define ABW (128 * GST)                  // A words per stage
#define WBW (64 * GST)                   // W words per stage
#define STGW (ABW + WBW)                 // 6912 words per stage
#define SMEM_GEMM (2 * STGW * 4)         // 55296 B

template <int MODE>
__global__ __launch_bounds__(128, 4) void gemm_f16(
    const uint32_t* __restrict__ A, const uint32_t* __restrict__ W,
    const float* __restrict__ bias, float* __restrict__ C,
    int M, int N, int Kw)
{
    extern __shared__ uint32_t gsm[];

    const int tid = threadIdx.x;
    const int lane = tid & 31;
    const int ww = tid >> 5;
    const int wr = ww >> 1;          // 0..1 (64-row band)
    const int wc = ww & 1;           // 0..1 (32-col band)
    const int qr = lane >> 2;
    const int qc = lane & 3;
    const int bm = blockIdx.y * 128;
    const int bn = blockIdx.x * 64;

    float acc[4][4][4];
#pragma unroll
    for (int i = 0; i < 4; i++)
#pragma unroll
        for (int j = 0; j < 4; j++)
#pragma unroll
            for (int c = 0; c < 4; c++) acc[i][j][c] = 0.0f;

    const uint32_t sm_base = (uint32_t)__cvta_generic_to_shared(gsm);
    const int nkt = Kw / 32;

    const uint32_t a_lane = (uint32_t)(((wr * 64 + (lane & 15)) * GST
                                        + (lane >> 4) * 4) * 4);
    const uint32_t b_lane = (uint32_t)(((wc * 32 + ((lane >> 4) << 3) + (lane & 7)) * GST
                                        + ((lane >> 3) & 1) * 4) * 4);

    auto stage = [&](int kt_idx, int s) {
#pragma unroll
        for (int i = 0; i < 8; i++) {       // A: 1024 chunks of 16B
            const int q = i * 128 + tid;
            const int r = q >> 3, c = q & 7;
            cp_async16(sm_base + (uint32_t)((s * STGW + r * GST + c * 4) * 4),
                       A + (size_t)(bm + r) * Kw + kt_idx * 32 + c * 4);
        }
#pragma unroll
        for (int i = 0; i < 4; i++) {       // W: 512 chunks
            const int q = i * 128 + tid;
            const int r = q >> 3, c = q & 7;
            cp_async16(sm_base + (uint32_t)((s * STGW + ABW + r * GST + c * 4) * 4),
                       W + (size_t)(bn + r) * Kw + kt_idx * 32 + c * 4);
        }
        cp_commit();
    };

    stage(0, 0);

    for (int kt = 0; kt < nkt; kt++) {
        const int s = kt & 1;
        __syncthreads();
        if (kt + 1 < nkt) { stage(kt + 1, s ^ 1); cp_wait<1>(); }
        else              { cp_wait<0>(); }
        __syncthreads();

        const uint32_t abase = sm_base + (uint32_t)(s * STGW * 4) + a_lane;
        const uint32_t bbase = sm_base + (uint32_t)((s * STGW + ABW) * 4) + b_lane;

#pragma unroll
        for (int st = 0; st < 4; st++) {
            uint32_t aa[4][4], bb[2][4];
#pragma unroll
            for (int mi = 0; mi < 4; mi++)
                ldsm_x4(abase + (uint32_t)(mi * 16 * GST * 4 + st * 32), aa[mi]);
#pragma unroll
            for (int p = 0; p < 2; p++)
                ldsm_x4(bbase + (uint32_t)(p * 16 * GST * 4 + st * 32), bb[p]);

#pragma unroll
            for (int mi = 0; mi < 4; mi++)
#pragma unroll
                for (int p = 0; p < 2; p++) {
                    mma_f16(acc[mi][2 * p],     aa[mi], bb[p][0], bb[p][1]);
                    mma_f16(acc[mi][2 * p + 1], aa[mi], bb[p][2], bb[p][3]);
                }
        }
    }

#pragma unroll
    for (int mi = 0; mi < 4; mi++) {
        const int row = bm + wr * 64 + mi * 16 + qr;
#pragma unroll
        for (int ni = 0; ni < 4; ni++) {
            const int col = bn + wc * 32 + ni * 8 + qc * 2;
            const float b0 = bias[col], b1 = bias[col + 1];
            float* d = acc[mi][ni];
            float v00 = d[0] + b0, v01 = d[1] + b1;
            float v10 = d[2] + b0, v11 = d[3] + b1;
            if (MODE == 1) {
                const float sc = (col < DD) ? QSCALE : 1.0f;
                v00 *= sc; v01 *= sc; v10 *= sc; v11 *= sc;
                const int w = col >> 1;
                uint32_t* C32 = (uint32_t*)C;
                C32[(size_t)row * (N >> 1) + w]       = pack_f16x2(v00, v01);
                C32[(size_t)(row + 8) * (N >> 1) + w] = pack_f16x2(v10, v11);
            } else {
                *(float2*)(C + (size_t)row * N + col)       = make_float2(v00, v01);
                *(float2*)(C + (size_t)(row + 8) * N + col) = make_float2(v10, v11);
            }
        }
    }
}

// ---------------------------------------------------------------------------
// Causal flash attention, fp16 mma + LDSM fragment feed.
// Grid (L/128, H, B) qt reversed, 4 warps, warp owns 32 q rows.
// K smem [seq][hd-words] stride 36 — B frags via ldmatrix.x4 (non-trans).
// V smem [seq][hd-words] stride 36 — B frags via ldmatrix.x4.TRANS
//   (HW transpose; no Vt scratch tensor, no transpose kernel).
// Q fragments gathered from linear global once. P packed from registers.
// ---------------------------------------------------------------------------
#define AST 36
#define TILE_WORDS (64 * AST)
#define OFF_K0 0
#define OFF_V0 (2 * TILE_WORDS)
#define SMEM_ATTN (4 * TILE_WORDS * 4)   // 36864 B

__global__ __launch_bounds__(128) void attn_f16_kernel(
    const float* __restrict__ qkvf, float* __restrict__ outf)
{
    extern __shared__ uint32_t sm[];
    const uint32_t* qkv = (const uint32_t*)qkvf;
    uint32_t* att = (uint32_t*)outf;

    const int qt = gridDim.x - 1 - blockIdx.x;
    const int h  = blockIdx.y;
    const int b  = blockIdx.z;

    const int tid = threadIdx.x;
    const int lane = tid & 31;
    const int wid = tid >> 5;
    const int qr = lane >> 2;
    const int qc = lane & 3;

    const uint32_t sm_base = (uint32_t)__cvta_generic_to_shared(sm);

    // ldmatrix lane offsets (stride AST):
    // K (non-trans B): lanes map n-rows / k-halves.
    const uint32_t bl_lane = (uint32_t)(((((lane >> 4) << 3) + (lane & 7)) * AST
                                         + ((lane >> 3) & 1) * 4) * 4);
    // V (trans B): lanes 0-15 -> seq rows 0-15 (hd words +0);
    //              lanes 16-31 -> same seq rows, hd words +4.
    const uint32_t vl_lane = (uint32_t)(((lane & 15) * AST + (lane >> 4) * 4) * 4);

    // Q fragments from linear global
    uint32_t qa[2][4][4];
    const uint32_t* qb = qkv + ((size_t)(b * LL + qt * 128 + wid * 32)) * 1536 + h * 32;
#pragma unroll
    for (int mi = 0; mi < 2; mi++)
#pragma unroll
        for (int ks = 0; ks < 4; ks++) {
            const size_t r0 = (size_t)(mi * 16 + qr) * 1536;
            qa[mi][ks][0] = qb[r0 + ks * 8 + qc];
            qa[mi][ks][1] = qb[r0 + 8 * 1536 + ks * 8 + qc];
            qa[mi][ks][2] = qb[r0 + ks * 8 + 4 + qc];
            qa[mi][ks][3] = qb[r0 + 8 * 1536 + ks * 8 + 4 + qc];
        }

    float o[2][8][4];
    float m[2][2], l[2][2];
#pragma unroll
    for (int mi = 0; mi < 2; mi++) {
        m[mi][0] = m[mi][1] = -INFINITY;
        l[mi][0] = l[mi][1] = 0.0f;
#pragma unroll
        for (int j = 0; j < 8; j++)
#pragma unroll
            for (int c = 0; c < 4; c++) o[mi][j][c] = 0.0f;
    }

    const int jmax = 2 * qt + 1;

    auto stage = [&](int jt, int s) {
        const uint32_t* kg = qkv + ((size_t)(b * LL + jt * 64)) * 1536 + 512 + h * 32;
        const uint32_t* vg = kg + 512;   // V section of the same rows
#pragma unroll
        for (int i = 0; i < 4; i++) {
            const int q = i * 128 + tid;
            const int r = q >> 3, c = q & 7;
            cp_async16(sm_base + (uint32_t)((OFF_K0 + s * TILE_WORDS + r * AST + c * 4) * 4),
                       kg + (size_t)r * 1536 + c * 4);
        }
#pragma unroll
        for (int i = 0; i < 4; i++) {
            const int q = i * 128 + tid;
            const int r = q >> 3, c = q & 7;
            cp_async16(sm_base + (uint32_t)((OFF_V0 + s * TILE_WORDS + r * AST + c * 4) * 4),
                       vg + (size_t)r * 1536 + c * 4);
        }
        cp_commit();
    };

    stage(0, 0);

    for (int jt = 0; jt <= jmax; jt++) {
        const int s = jt & 1;
        __syncthreads();
        if (jt + 1 <= jmax) { stage(jt + 1, s ^ 1); cp_wait<1>(); }
        else                { cp_wait<0>(); }
        __syncthreads();

        const uint32_t kbase = sm_base + (uint32_t)((OFF_K0 + s * TILE_WORDS) * 4) + bl_lane;
        const uint32_t vbase = sm_base + (uint32_t)((OFF_V0 + s * TILE_WORDS) * 4) + vl_lane;

        const int wrow_min = qt * 128 + wid * 32;
        const bool tile_dead = (jt * 64) > (wrow_min + 31);

        if (!tile_dead) {
            // S = Q K^T  (K B-fragments via LDSM)
            float sreg[2][8][4];
#pragma unroll
            for (int mi = 0; mi < 2; mi++)
#pragma unroll
                for (int j = 0; j < 8; j++)
#pragma unroll
                    for (int c = 0; c < 4; c++) sreg[mi][j][c] = 0.0f;

#pragma unroll
            for (int jj = 0; jj < 4; jj++) {        // 16 seq rows per jj
#pragma unroll
                for (int ks = 0; ks < 4; ks++) {
                    uint32_t kb[4];
                    ldsm_x4(kbase + (uint32_t)(jj * 16 * AST * 4 + ks * 32), kb);
                    mma_f16(sreg[0][2 * jj],     qa[0][ks], kb[0], kb[1]);
                    mma_f16(sreg[1][2 * jj],     qa[1][ks], kb[0], kb[1]);
                    mma_f16(sreg[0][2 * jj + 1], qa[0][ks], kb[2], kb[3]);
                    mma_f16(sreg[1][2 * jj + 1], qa[1][ks], kb[2], kb[3]);
                }
            }

            // causal mask
            if ((jt + 1) * 64 - 1 > wrow_min) {
#pragma unroll
                for (int mi = 0; mi < 2; mi++) {
                    const int r0 = wrow_min + mi * 16 + qr;
#pragma unroll
                    for (int j = 0; j < 8; j++) {
                        const int c0 = jt * 64 + j * 8 + qc * 2;
                        if (c0     > r0)     sreg[mi][j][0] = -INFINITY;
                        if (c0 + 1 > r0)     sreg[mi][j][1] = -INFINITY;
                        if (c0     > r0 + 8) sreg[mi][j][2] = -INFINITY;
                        if (c0 + 1 > r0 + 8) sreg[mi][j][3] = -INFINITY;
                    }
                }
            }

            // online softmax (base 2)
#pragma unroll
            for (int mi = 0; mi < 2; mi++) {
                float mt0 = -INFINITY, mt1 = -INFINITY;
#pragma unroll
                for (int j = 0; j < 8; j++) {
                    mt0 = fmaxf(mt0, fmaxf(sreg[mi][j][0], sreg[mi][j][1]));
                    mt1 = fmaxf(mt1, fmaxf(sreg[mi][j][2], sreg[mi][j][3]));
                }
#pragma unroll
                for (int off = 1; off <= 2; off <<= 1) {
                    mt0 = fmaxf(mt0, __shfl_xor_sync(0xffffffffu, mt0, off));
                    mt1 = fmaxf(mt1, __shfl_xor_sync(0xffffffffu, mt1, off));
                }
                const float mn0 = fmaxf(m[mi][0], mt0);
                const float mn1 = fmaxf(m[mi][1], mt1);
                const float al0 = exp2f(m[mi][0] - mn0);
                const float al1 = exp2f(m[mi][1] - mn1);
                m[mi][0] = mn0; m[mi][1] = mn1;
                float rs0 = 0.0f, rs1 = 0.0f;
#pragma unroll
                for (int j = 0; j < 8; j++) {
                    sreg[mi][j][0] = exp2f(sreg[mi][j][0] - mn0);
                    sreg[mi][j][1] = exp2f(sreg[mi][j][1] - mn0);
                    sreg[mi][j][2] = exp2f(sreg[mi][j][2] - mn1);
                    sreg[mi][j][3] = exp2f(sreg[mi][j][3] - mn1);
                    rs0 += sreg[mi][j][0] + sreg[mi][j][1];
                    rs1 += sreg[mi][j][2] + sreg[mi][j][3];
                }
#pragma unroll
                for (int off = 1; off <= 2; off <<= 1) {
                    rs0 += __shfl_xor_sync(0xffffffffu, rs0, off);
                    rs1 += __shfl_xor_sync(0xffffffffu, rs1, off);
                }
                l[mi][0] = l[mi][0] * al0 + rs0;
                l[mi][1] = l[mi][1] * al1 + rs1;
#pragma unroll
                for (int j = 0; j < 8; j++) {
                    o[mi][j][0] *= al0; o[mi][j][1] *= al0;
                    o[mi][j][2] *= al1; o[mi][j][3] *= al1;
                }
            }

            // pack P A-fragments (per ks16 step)
            uint32_t pa[2][4][4];
#pragma unroll
            for (int mi = 0; mi < 2; mi++)
#pragma unroll
                for (int ks = 0; ks < 4; ks++) {
                    pa[mi][ks][0] = pack_f16x2(sreg[mi][2 * ks][0],     sreg[mi][2 * ks][1]);
                    pa[mi][ks][1] = pack_f16x2(sreg[mi][2 * ks][2],     sreg[mi][2 * ks][3]);
                    pa[mi][ks][2] = pack_f16x2(sreg[mi][2 * ks + 1][0], sreg[mi][2 * ks + 1][1]);
                    pa[mi][ks][3] = pack_f16x2(sreg[mi][2 * ks + 1][2], sreg[mi][2 * ks + 1][3]);
                }

            // O += P @ V  (V B-fragments via LDSM-trans, straight from [seq][hd])
#pragma unroll
            for (int jj = 0; jj < 4; jj++) {        // hd 16-block jj
#pragma unroll
                for (int ks = 0; ks < 4; ks++) {    // seq 16-block ks
                    uint32_t vb[4];
                    ldsm_x4_t(vbase + (uint32_t)((ks * 16 * AST + jj * 8) * 4), vb);
                    mma_f16(o[0][2 * jj],     pa[0][ks], vb[0], vb[1]);
                    mma_f16(o[1][2 * jj],     pa[1][ks], vb[0], vb[1]);
                    mma_f16(o[0][2 * jj + 1], pa[0][ks], vb[2], vb[3]);
                    mma_f16(o[1][2 * jj + 1], pa[1][ks], vb[2], vb[3]);
                }
            }
        }
    }

    // epilogue: LINEAR word layout
    const int orow0 = b * LL + qt * 128 + wid * 32;
#pragma unroll
    for (int mi = 0; mi < 2; mi++) {
        const float inv0 = 1.0f / l[mi][0];
        const float inv1 = 1.0f / l[mi][1];
        const size_t r0 = (size_t)(orow0 + mi * 16 + qr) * 512;
#pragma unroll
        for (int j = 0; j < 8; j++) {
            const int wp = h * 32 + j * 4 + qc;
            att[r0 + wp]           = pack_f16x2(o[mi][j][0] * inv0, o[mi][j][1] * inv0);
            att[r0 + 8 * 512 + wp] = pack_f16x2(o[mi][j][2] * inv1, o[mi][j][3] * inv1);
        }
    }
}

// ---------------------------------------------------------------------------
extern "C" void kernel_launch(void* const* d_in, const int* in_sizes, int n_in,
                              void* d_out, int out_size)
{
    const float* x    = (const float*)d_in[0];
    const float* Wqkv = (const float*)d_in[1];
    const float* bqkv = (const float*)d_in[2];
    const float* Wout = (const float*)d_in[3];
    const float* bout = (const float*)d_in[4];
    float* outp = (float*)d_out;

    float *qkv = nullptr, *att = nullptr;
    uint32_t *xt = nullptr, *wq = nullptr, *wo = nullptr;
    cudaGetSymbolAddress((void**)&qkv, g_qkv);
    cudaGetSymbolAddress((void**)&att, g_att);
    cudaGetSymbolAddress((void**)&xt, g_xt);
    cudaGetSymbolAddress((void**)&wq, g_wq);
    cudaGetSymbolAddress((void**)&wo, g_wo);

    static bool attr_set = false;
    if (!attr_set) {
        cudaFuncSetAttribute(attn_f16_kernel,
                             cudaFuncAttributeMaxDynamicSharedMemorySize, SMEM_ATTN);
        cudaFuncSetAttribute(gemm_f16<0>,
                             cudaFuncAttributeMaxDynamicSharedMemorySize, SMEM_GEMM);
        cudaFuncSetAttribute(gemm_f16<1>,
                             cudaFuncAttributeMaxDynamicSharedMemorySize, SMEM_GEMM);
        attr_set = true;
    }

    const int M = BB * LL;   // 8192
    const int Kw = DD / 2;   // 512 words

    // prepass: single launch, fp32 -> fp16 for x, Wqkv, Wout (linear)
    {
        const int n1 = (M * DD) / 8;
        const int n2 = (3 * DD * DD) / 8;
        const int n3 = (DD * DD) / 8;
        const int nt = n1 + n2 + n3;
        conv_f16_all<<<(nt + 255) / 256, 256>>>(x, xt, Wqkv, wq, Wout, wo,
                                                n1, n2, n3);
    }

    // 1) QKV projection (fp16 words out; Q scaled; all linear)
    {
        dim3 grid((3 * DD) / 64, M / 128);
        gemm_f16<1><<<grid, 128, SMEM_GEMM>>>(xt, wq, bqkv, qkv, M, 3 * DD, Kw);
    }

    // 2) causal attention (V transposed in-flight by ldmatrix.trans)
    {
        dim3 grid(LL / 128, HH, BB);
        attn_f16_kernel<<<grid, 128, SMEM_ATTN>>>(qkv, att);
    }

    // 3) output projection (fp32 out)
    {
        dim3 grid(DD / 64, M / 128);
        gemm_f16<0><<<grid, 128, SMEM_GEMM>>>((const uint32_t*)att, wo, bout, outp,
                                              M, DD, Kw);
    }
}